// round 15
// baseline (speedup 1.0000x reference)
#include <cuda_runtime.h>
#include <cuda_bf16.h>
#include <math.h>
#include <stdint.h>

#define BB 8
#define CINN 3
#define DM 512
#define N2C 32
#define NLAY 4
#define LL 4096
#define LAT 256
#define NCH 16      // chunks per sequence
#define CH 256      // chunk length

// ---------------- scratch (device globals; no allocation allowed) -------------
__device__ float g_h[BB * DM * LL];              // PRE-LN residuals [b][d][l]
__device__ __nv_bfloat16 g_yth[BB * LL * DM];    // Y^T hi  [b][l][d]
__device__ __nv_bfloat16 g_wh[NLAY * 2 * DM * DM];
__device__ __nv_bfloat16 g_wl[NLAY * 2 * DM * DM];
__device__ float g_wre[NLAY * DM * N2C];
__device__ float g_wim[NLAY * DM * N2C];
__device__ float g_cre[NLAY * DM * N2C];
__device__ float g_cim[NLAY * DM * N2C];
__device__ float g_wpre[NLAY * DM * N2C];        // w^CH real
__device__ float g_wpim[NLAY * DM * N2C];        // w^CH imag
__device__ float g_bnd[BB * DM * NCH * N2C * 2]; // chunk remainders r_c
// ping-pong LN stats: raw (sum,sumsq) -> after lnfix (rs, -mu*rs), per (b,l)
__device__ float g_lnst[2 * BB * LL * 2];
__device__ float g_hbar[BB * DM];

// ---------------- helpers -----------------------------------------------------
__device__ __forceinline__ uint32_t smem_u32(const void* p) {
    uint32_t a;
    asm("{ .reg .u64 t; cvta.to.shared.u64 t, %1; cvt.u32.u64 %0, t; }" : "=r"(a) : "l"(p));
    return a;
}
#define SW128(o) ((o) ^ (((o) >> 3) & 0x70))

#define LDMX4(r, addr) \
    asm volatile("ldmatrix.sync.aligned.m8n8.x4.shared.b16 {%0,%1,%2,%3}, [%4];" \
        : "=r"((r)[0]), "=r"((r)[1]), "=r"((r)[2]), "=r"((r)[3]) : "r"(addr))

#define MMA16816(c, a, b) \
    asm volatile("mma.sync.aligned.m16n8k16.row.col.f32.bf16.bf16.f32 " \
        "{%0,%1,%2,%3}, {%4,%5,%6,%7}, {%8,%9}, {%0,%1,%2,%3};" \
        : "+f"((c)[0]), "+f"((c)[1]), "+f"((c)[2]), "+f"((c)[3]) \
        : "r"((a)[0]), "r"((a)[1]), "r"((a)[2]), "r"((a)[3]), \
          "r"((b)[0]), "r"((b)[1]))

__device__ __forceinline__ void cpa16(uint32_t dst, const void* src) {
    asm volatile("cp.async.cg.shared.global [%0], [%1], 16;" :: "r"(dst), "l"(src));
}

// ---- packed fp32x2 (Blackwell FFMA2 path) ----
#define PK2(d, a, b) \
    asm("mov.b64 %0, {%1, %2};" : "=l"(d) : "r"(__float_as_uint(a)), "r"(__float_as_uint(b)))
#define UPK2(a, b, d) \
    { uint32_t _x, _y; asm("mov.b64 {%0, %1}, %2;" : "=r"(_x), "=r"(_y) : "l"(d)); \
      (a) = __uint_as_float(_x); (b) = __uint_as_float(_y); }
#define FMA2(d, a, b, c) \
    asm("fma.rn.f32x2 %0, %1, %2, %3;" : "=l"(d) : "l"(a), "l"(b), "l"(c))
#define MUL2(d, a, b) \
    asm("mul.rn.f32x2 %0, %1, %2;" : "=l"(d) : "l"(a), "l"(b))

// ---------------- kernel 0: per-layer SSM parameter precompute ----------------
__global__ void precompute_kernel(const float* __restrict__ log_dt,
                                  const float* __restrict__ log_A_real,
                                  const float* __restrict__ A_imag,
                                  const float* __restrict__ C_re,
                                  const float* __restrict__ C_im)
{
    int idx = blockIdx.x * blockDim.x + threadIdx.x;
    if (idx >= NLAY * DM * N2C) return;
    int hd = idx / N2C;
    float dt  = expf(log_dt[hd]);
    float are = -expf(log_A_real[idx]);
    float aim = A_imag[idx];
    float dre = are * dt;
    float dim = aim * dt;
    float er  = expf(dre);
    float wre = er * cosf(dim);
    float wim = er * sinf(dim);
    float Ere = wre - 1.0f;
    float Eim = wim;
    float inv = 1.0f / (are * are + aim * aim);
    float fre = (Ere * are + Eim * aim) * inv;
    float fim = (Eim * are - Ere * aim) * inv;
    float crr = C_re[idx], cii = C_im[idx];
    g_wre[idx] = wre;
    g_wim[idx] = wim;
    g_cre[idx] = 2.0f * (crr * fre - cii * fim);
    g_cim[idx] = 2.0f * (crr * fim + cii * fre);
    float pr = expf((float)CH * dre);
    g_wpre[idx] = pr * cosf((float)CH * dim);
    g_wpim[idx] = pr * sinf((float)CH * dim);
}

// ---------------- kernel 0b: bf16-split Wout ----------------------------------
__global__ void wsplit_kernel(const float* __restrict__ Wout)
{
    int idx = blockIdx.x * blockDim.x + threadIdx.x;
    if (idx >= NLAY * 2 * DM * DM) return;
    float v = Wout[idx];
    __nv_bfloat16 h = __float2bfloat16(v);
    g_wh[idx] = h;
    g_wl[idx] = __float2bfloat16(v - __bfloat162float(h));
}

// ---------------- kernel 1: input projection + positional embedding ----------
__global__ void proj_kernel(const float* __restrict__ x,
                            const float* __restrict__ Wproj,
                            const float* __restrict__ bproj,
                            const float* __restrict__ pos)
{
    int idx = blockIdx.x * blockDim.x + threadIdx.x;
    if (idx >= BB * DM * LL) return;
    int l = idx & (LL - 1);
    int d = (idx >> 12) & (DM - 1);
    int b = idx >> 21;
    const float* xb = x + (size_t)b * CINN * LL;
    float v = bproj[d];
    v = fmaf(Wproj[d * 3 + 0], xb[l], v);
    v = fmaf(Wproj[d * 3 + 1], xb[LL + l], v);
    v = fmaf(Wproj[d * 3 + 2], xb[2 * LL + l], v);
    v += pos[(size_t)l * DM + d];
    g_h[idx] = v;
}

// ---------------- kernel 2a: chunk remainders, 4-step-blocked + lazy LN -------
__global__ void scanA_kernel(const float* __restrict__ ln_g,
                             const float* __restrict__ ln_b, int layer)
{
    int gtid = blockIdx.x * blockDim.x + threadIdx.x;
    if (gtid < BB * LL * 2) g_lnst[(layer & 1) * (BB * LL * 2) + gtid] = 0.f;

    int pair = gtid >> 3;
    int r    = gtid & 7;
    int ch    = pair / (NCH - 1);
    int chunk = pair % (NCH - 1);
    int d = ch & (DM - 1);
    int b = ch >> 9;

    int pbase = (layer * DM + d) * N2C + 4 * r;
    float a1r[4], a1i[4], a2r[4], a2i[4], a3r[4], a3i[4], a4r[4], a4i[4];
#pragma unroll
    for (int q = 0; q < 4; q++) {
        a1r[q] = g_wre[pbase + q];
        a1i[q] = g_wim[pbase + q];
        a2r[q] = a1r[q] * a1r[q] - a1i[q] * a1i[q];
        a2i[q] = 2.0f * a1r[q] * a1i[q];
        a3r[q] = a2r[q] * a1r[q] - a2i[q] * a1i[q];
        a3i[q] = a2r[q] * a1i[q] + a2i[q] * a1r[q];
        a4r[q] = a2r[q] * a2r[q] - a2i[q] * a2i[q];
        a4i[q] = 2.0f * a2r[q] * a2i[q];
    }
    uint64_t w1re2[2], w1im2[2], w2re2[2], w2im2[2], w3re2[2], w3im2[2];
    uint64_t w4re2[2], w4im2[2], nw4im2[2];
#pragma unroll
    for (int p = 0; p < 2; p++) {
        PK2(w1re2[p], a1r[2 * p], a1r[2 * p + 1]);
        PK2(w1im2[p], a1i[2 * p], a1i[2 * p + 1]);
        PK2(w2re2[p], a2r[2 * p], a2r[2 * p + 1]);
        PK2(w2im2[p], a2i[2 * p], a2i[2 * p + 1]);
        PK2(w3re2[p], a3r[2 * p], a3r[2 * p + 1]);
        PK2(w3im2[p], a3i[2 * p], a3i[2 * p + 1]);
        PK2(w4re2[p], a4r[2 * p], a4r[2 * p + 1]);
        PK2(w4im2[p], a4i[2 * p], a4i[2 * p + 1]);
        PK2(nw4im2[p], -a4i[2 * p], -a4i[2 * p + 1]);
    }

    const bool lnok = (layer > 0);
    float gd = 1.f, bd = 0.f;
    const float2* lnp = nullptr;
    if (lnok) {
        gd = ln_g[(layer - 1) * DM + d];
        bd = ln_b[(layer - 1) * DM + d];
        lnp = (const float2*)g_lnst + ((layer + 1) & 1) * (BB * LL)
            + (size_t)b * LL + chunk * CH;
    }

    const float* u = g_h + (size_t)ch * LL + chunk * CH;
    uint64_t sre2[2] = {0ull, 0ull}, sim2[2] = {0ull, 0ull};

    for (int base = 0; base < CH; base += 32) {
        float4 f4[8];
        const float4* up = (const float4*)(u + base);
#pragma unroll
        for (int i = 0; i < 8; i++) f4[i] = up[i];
        if (lnok) {
            const float2* lq = lnp + base;
#pragma unroll
            for (int i = 0; i < 8; i++) {
                float2 l0 = lq[4 * i], l1 = lq[4 * i + 1];
                float2 l2 = lq[4 * i + 2], l3 = lq[4 * i + 3];
                f4[i].x = fmaf(fmaf(f4[i].x, l0.x, l0.y), gd, bd);
                f4[i].y = fmaf(fmaf(f4[i].y, l1.x, l1.y), gd, bd);
                f4[i].z = fmaf(fmaf(f4[i].z, l2.x, l2.y), gd, bd);
                f4[i].w = fmaf(fmaf(f4[i].w, l3.x, l3.y), gd, bd);
            }
        }
#pragma unroll
        for (int i = 0; i < 8; i++) {
            float4 q = f4[i];
            uint64_t ux, uy, uz, uw;
            PK2(ux, q.x, q.x);
            PK2(uy, q.y, q.y);
            PK2(uz, q.z, q.z);
            PK2(uw, q.w, q.w);
#pragma unroll
            for (int p = 0; p < 2; p++) {
                uint64_t vre, vim, rr, xx, nre, nim;
                FMA2(vre, w3re2[p], ux, uw);
                FMA2(vre, w2re2[p], uy, vre);
                FMA2(vre, w1re2[p], uz, vre);
                MUL2(vim, w3im2[p], ux);
                FMA2(vim, w2im2[p], uy, vim);
                FMA2(vim, w1im2[p], uz, vim);
                FMA2(xx, w4im2[p], sre2[p], vim);
                FMA2(rr, nw4im2[p], sim2[p], vre);
                FMA2(nre, w4re2[p], sre2[p], rr);
                FMA2(nim, w4re2[p], sim2[p], xx);
                sre2[p] = nre;
                sim2[p] = nim;
            }
        }
    }
    float* bnd = g_bnd + ((size_t)ch * NCH + chunk) * 64 + 8 * r;
#pragma unroll
    for (int p = 0; p < 2; p++) {
        float r0, r1, i0, i1;
        UPK2(r0, r1, sre2[p]);
        UPK2(i0, i1, sim2[p]);
        bnd[4 * p + 0] = r0;
        bnd[4 * p + 1] = i0;
        bnd[4 * p + 2] = r1;
        bnd[4 * p + 3] = i1;
    }
}

// ---------------- kernel 2c: 2-step output scan + GELU + fused transp/split ---
__global__ void scanC_kernel(const float* __restrict__ Dskip,
                             const float* __restrict__ ln_g,
                             const float* __restrict__ ln_b, int layer)
{
    __shared__ float tile[32][65];
    __shared__ float sSre[32][32];
    __shared__ float sSim[32][32];
    int tid  = threadIdx.x;
    int wid  = tid >> 5;
    int lane = tid & 31;
    int g = lane >> 3;
    int r = lane & 7;
    int chunk = blockIdx.x;
    int chgrp = blockIdx.y;
    int chl = wid * 4 + g;
    int chn = chgrp * 32 + chl;
    int d = chn & (DM - 1);
    int b = chn >> 9;
    int d0 = (chgrp & 15) * 32;

    // ---- prologue: incoming state S_chunk for all 32 channels x 32 n
    {
#pragma unroll
        for (int it = 0; it < 4; it++) {
            int pid = tid + 256 * it;
            int pc = pid >> 5;
            int n  = pid & 31;
            int pch = chgrp * 32 + pc;
            int pd  = pch & (DM - 1);
            float wpre = g_wpre[(layer * DM + pd) * N2C + n];
            float wpim = g_wpim[(layer * DM + pd) * N2C + n];
            float Sre = 0.f, Sim = 0.f;
            const float* bnd = g_bnd + (size_t)pch * NCH * 64 + 2 * n;
            for (int k = 0; k < chunk; k++) {
                float rre = bnd[k * 64];
                float rim = bnd[k * 64 + 1];
                float nre = fmaf(wpre, Sre, fmaf(-wpim, Sim, rre));
                Sim = fmaf(wpre, Sim, fmaf(wpim, Sre, rim));
                Sre = nre;
            }
            sSre[pc][n] = Sre;
            sSim[pc][n] = Sim;
        }
        __syncthreads();
    }

    int pbase = (layer * DM + d) * N2C + 4 * r;
    uint64_t w1re2[2], w1im2[2], w2re2[2], w2im2[2], nw2im2[2];
    uint64_t cre2[2], ncim2[2], c1re2[2], nc1im2[2];
    float k0lane = 0.f;
#pragma unroll
    for (int p = 0; p < 2; p++) {
        float wr0 = g_wre[pbase + 2 * p], wr1 = g_wre[pbase + 2 * p + 1];
        float wi0 = g_wim[pbase + 2 * p], wi1 = g_wim[pbase + 2 * p + 1];
        float cr0 = g_cre[pbase + 2 * p], cr1 = g_cre[pbase + 2 * p + 1];
        float ci0 = g_cim[pbase + 2 * p], ci1 = g_cim[pbase + 2 * p + 1];
        float w2r0 = wr0 * wr0 - wi0 * wi0, w2r1 = wr1 * wr1 - wi1 * wi1;
        float w2i0 = 2.f * wr0 * wi0,       w2i1 = 2.f * wr1 * wi1;
        float c1r0 = cr0 * wr0 - ci0 * wi0, c1r1 = cr1 * wr1 - ci1 * wi1;
        float c1i0 = cr0 * wi0 + ci0 * wr0, c1i1 = cr1 * wi1 + ci1 * wr1;
        PK2(w1re2[p], wr0, wr1);
        PK2(w1im2[p], wi0, wi1);
        PK2(w2re2[p], w2r0, w2r1);
        PK2(w2im2[p], w2i0, w2i1);
        PK2(nw2im2[p], -w2i0, -w2i1);
        PK2(cre2[p], cr0, cr1);
        PK2(ncim2[p], -ci0, -ci1);
        PK2(c1re2[p], c1r0, c1r1);
        PK2(nc1im2[p], -c1i0, -c1i1);
        k0lane += cr0 + cr1;
    }
    float dsk = Dskip[layer * DM + d];

    const bool lnok = (layer > 0);
    float gd = 1.f, bd = 0.f;
    const float2* lnp = nullptr;
    if (lnok) {
        gd = ln_g[(layer - 1) * DM + d];
        bd = ln_b[(layer - 1) * DM + d];
        lnp = (const float2*)g_lnst + ((layer + 1) & 1) * (BB * LL)
            + (size_t)b * LL + chunk * CH;
    }

    uint64_t sre2[2], sim2[2];
#pragma unroll
    for (int p = 0; p < 2; p++) {
        PK2(sre2[p], sSre[chl][4 * r + 2 * p], sSre[chl][4 * r + 2 * p + 1]);
        PK2(sim2[p], sSim[chl][4 * r + 2 * p], sSim[chl][4 * r + 2 * p + 1]);
    }
    __syncthreads();

    const float* u = g_h + (size_t)chn * LL + chunk * CH;
    size_t outrow0 = ((size_t)b * LL + chunk * CH) * DM + d0;

    for (int base = 0; base < CH; base += 32) {
        float uv[4];
#pragma unroll
        for (int k = 0; k < 4; k++) uv[k] = u[base + r + 8 * k];
        if (lnok) {
#pragma unroll
            for (int k = 0; k < 4; k++) {
                float2 lp = lnp[base + r + 8 * k];
                uv[k] = fmaf(fmaf(uv[k], lp.x, lp.y), gd, bd);
            }
        }
        float yr[4] = {0.f, 0.f, 0.f, 0.f};
#pragma unroll
        for (int j = 0; j < 32; j += 2) {
            float uu1 = __shfl_sync(0xffffffffu, uv[j >> 3], (j & 7), 8);
            float uu2 = __shfl_sync(0xffffffffu, uv[(j + 1) >> 3], ((j + 1) & 7), 8);
            uint64_t u1p, u2p;
            PK2(u1p, uu1, uu1);
            PK2(u2p, uu2, uu2);
            uint64_t c1a = 0ull, c2a = 0ull;
#pragma unroll
            for (int p = 0; p < 2; p++) {
                // y1 from old state s0
                FMA2(c1a, c1re2[p], sre2[p], c1a);
                FMA2(c1a, nc1im2[p], sim2[p], c1a);
                // v = w*u1 + u2
                uint64_t vre, vim, xx, rr, nre, nim;
                FMA2(vre, w1re2[p], u1p, u2p);
                MUL2(vim, w1im2[p], u1p);
                // s2 = w^2 * s0 + v
                FMA2(xx, w2im2[p], sre2[p], vim);
                FMA2(rr, nw2im2[p], sim2[p], vre);
                FMA2(nre, w2re2[p], sre2[p], rr);
                FMA2(nim, w2re2[p], sim2[p], xx);
                sre2[p] = nre;
                sim2[p] = nim;
                // y2 from new state
                FMA2(c2a, cre2[p], nre, c2a);
                FMA2(c2a, ncim2[p], nim, c2a);
            }
            float l1, h1, l2, h2;
            UPK2(l1, h1, c1a);
            UPK2(l2, h2, c2a);
            float y1 = fmaf(k0lane, uu1, l1 + h1);
            float y2 = l2 + h2;
            y1 += __shfl_xor_sync(0xffffffffu, y1, 4);
            y1 += __shfl_xor_sync(0xffffffffu, y1, 2);
            y1 += __shfl_xor_sync(0xffffffffu, y1, 1);
            y2 += __shfl_xor_sync(0xffffffffu, y2, 4);
            y2 += __shfl_xor_sync(0xffffffffu, y2, 2);
            y2 += __shfl_xor_sync(0xffffffffu, y2, 1);
            if (r == (j & 7)) yr[j >> 3] = y1;
            if (r == ((j + 1) & 7)) yr[(j + 1) >> 3] = y2;
        }
        int off = base & 32;
#pragma unroll
        for (int k = 0; k < 4; k++) {
            float v = fmaf(dsk, uv[k], yr[k]);
            float ge = 0.5f * v * (1.0f + erff(v * 0.70710678118654752f));
            tile[chl][off + r + 8 * k] = ge;
        }
        if (base & 32) {
            __syncthreads();
            int w0 = base - 32;
            int ll = tid >> 2;
            int dd0 = (tid & 3) * 8;
            __align__(16) __nv_bfloat16 hh[8];
#pragma unroll
            for (int i = 0; i < 8; i++)
                hh[i] = __float2bfloat16(tile[dd0 + i][ll]);
            size_t dst = outrow0 + (size_t)(w0 + ll) * DM + dd0;
            *(uint4*)(g_yth + dst) = *(uint4*)hh;
            __syncthreads();
        }
    }
}

// ---------------- kernel 3: HMMA GEMM + lazy-LN residual + GLU + LN stats -----
#define STAGE 49152
#define OFF_AH 0
#define OFF_AL 16384
#define OFF_BH 32768

__global__ void __launch_bounds__(256, 2)
gemm_mma_kernel(const float* __restrict__ bout,
                const float* __restrict__ ln_g,
                const float* __restrict__ ln_b, int layer)
{
    extern __shared__ char dsm[];
    uint32_t sb = smem_u32(dsm);

    const int tid  = threadIdx.x;
    const int wid  = tid >> 5;
    const int lane = tid & 31;
    const int wm   = wid >> 2;
    const int wn   = wid & 3;
    const int n0   = blockIdx.x * 128;
    const int m0   = blockIdx.y * 64;
    const int bb   = blockIdx.z;

    const __nv_bfloat16* Wh = g_wh + (size_t)layer * 2 * DM * DM;
    const __nv_bfloat16* Wl = g_wl + (size_t)layer * 2 * DM * DM;
    const __nv_bfloat16* Bh = g_yth + (size_t)bb * LL * DM;

    auto load_stage = [&](int c) {
        int buf = c & 1;
        int kb = c * 64;
        uint32_t base = sb + buf * STAGE;
#pragma unroll
        for (int i = 0; i < 4; i++) {
            int v = tid + (i << 8);
            int row = v >> 3;
            int seg = v & 7;
            uint32_t dsw = SW128((uint32_t)(row * 128 + seg * 16));
            int p = (row < 64) ? (m0 + row) : (448 + m0 + row);
            size_t ao = (size_t)p * DM + kb + seg * 8;
            cpa16(base + OFF_AH + dsw, Wh + ao);
            cpa16(base + OFF_AL + dsw, Wl + ao);
            size_t bo = (size_t)(n0 + row) * DM + kb + seg * 8;
            cpa16(base + OFF_BH + dsw, Bh + bo);
        }
        asm volatile("cp.async.commit_group;" ::: "memory");
    };

    float acc[4][4][4];
#pragma unroll
    for (int i = 0; i < 4; i++)
#pragma unroll
        for (int j = 0; j < 4; j++)
#pragma unroll
            for (int k = 0; k < 4; k++) acc[i][j][k] = 0.f;

    load_stage(0);
    load_stage(1);

    for (int s = 0; s < 8; ++s) {
        if (s < 7) asm volatile("cp.async.wait_group 1;" ::: "memory");
        else       asm volatile("cp.async.wait_group 0;" ::: "memory");
        __syncthreads();

        uint32_t base = sb + (s & 1) * STAGE;
#pragma unroll
        for (int k16 = 0; k16 < 4; ++k16) {
            uint32_t ah[4][4], al[4][4], bhf[4][2];
#pragma unroll
            for (int mf = 0; mf < 4; ++mf) {
                int rowbase = (mf < 2) ? (wm * 32 + mf * 16)
                                       : (64 + wm * 32 + (mf - 2) * 16);
                int row = rowbase + (lane & 15);
                uint32_t off = SW128((uint32_t)(row * 128 + k16 * 32 + ((lane >> 4) << 4)));
                LDMX4(ah[mf], base + OFF_AH + off);
                LDMX4(al[mf], base + OFF_AL + off);
            }
#pragma unroll
            for (int pr = 0; pr < 2; ++pr) {
                int row = wn * 32 + pr * 16 + (lane & 7) + ((lane >> 4) << 3);
                uint32_t off = SW128((uint32_t)(row * 128 + k16 * 32 + (((lane >> 3) & 1) << 4)));
                uint32_t t[4];
                LDMX4(t, base + OFF_BH + off);
                bhf[2 * pr][0] = t[0]; bhf[2 * pr][1] = t[1];
                bhf[2 * pr + 1][0] = t[2]; bhf[2 * pr + 1][1] = t[3];
            }
#pragma unroll
            for (int mf = 0; mf < 4; ++mf)
#pragma unroll
                for (int nf = 0; nf < 4; ++nf) {
                    MMA16816(acc[mf][nf], ah[mf], bhf[nf]);
                    MMA16816(acc[mf][nf], al[mf], bhf[nf]);
                }
        }
        __syncthreads();
        if (s < 6) load_stage(s + 2);
    }

    const float* bo = bout + layer * 2 * DM;
    int groupid = lane >> 2;
    int tg = lane & 3;

    const bool lnok = (layer > 0);
    float2 lpr[4][2];
    if (lnok) {
        const float2* lnq = (const float2*)g_lnst + ((layer + 1) & 1) * (BB * LL)
                          + (size_t)bb * LL;
#pragma unroll
        for (int nf = 0; nf < 4; ++nf) {
            float4 t = *(const float4*)(lnq + n0 + wn * 32 + nf * 8 + tg * 2);
            lpr[nf][0] = make_float2(t.x, t.y);
            lpr[nf][1] = make_float2(t.z, t.w);
        }
    }

    float sacc[4][2], s2acc[4][2];
#pragma unroll
    for (int nf = 0; nf < 4; nf++) {
        sacc[nf][0] = 0.f; sacc[nf][1] = 0.f;
        s2acc[nf][0] = 0.f; s2acc[nf][1] = 0.f;
    }
#pragma unroll
    for (int mf = 0; mf < 2; ++mf) {
#pragma unroll
        for (int rp = 0; rp < 2; ++rp) {
            int o = m0 + wm * 32 + mf * 16 + groupid + rp * 8;
            float b1 = bo[o];
            float b2 = bo[DM + o];
            float go = 1.f, bo2 = 0.f;
            if (lnok) {
                go  = ln_g[(layer - 1) * DM + o];
                bo2 = ln_b[(layer - 1) * DM + o];
            }
            float* H = g_h + ((size_t)bb * DM + o) * LL + n0 + wn * 32;
#pragma unroll
            for (int nf = 0; nf < 4; ++nf) {
                float a0 = acc[mf][nf][rp * 2 + 0] + b1;
                float a1 = acc[mf][nf][rp * 2 + 1] + b1;
                float g0 = acc[mf + 2][nf][rp * 2 + 0] + b2;
                float g1 = acc[mf + 2][nf][rp * 2 + 1] + b2;
                float z0 = a0 / (1.0f + expf(-g0));
                float z1 = a1 / (1.0f + expf(-g1));
                float2* ptr = (float2*)(H + nf * 8 + tg * 2);
                float2 h2 = *ptr;
                if (lnok) {
                    h2.x = fmaf(fmaf(h2.x, lpr[nf][0].x, lpr[nf][0].y), go, bo2);
                    h2.y = fmaf(fmaf(h2.y, lpr[nf][1].x, lpr[nf][1].y), go, bo2);
                }
                h2.x += z0;
                h2.y += z1;
                *ptr = h2;
                sacc[nf][0] += h2.x;
                s2acc[nf][0] = fmaf(h2.x, h2.x, s2acc[nf][0]);
                sacc[nf][1] += h2.y;
                s2acc[nf][1] = fmaf(h2.y, h2.y, s2acc[nf][1]);
            }
        }
    }
    float* lncur = g_lnst + (layer & 1) * (BB * LL * 2);
#pragma unroll
    for (int nf = 0; nf < 4; ++nf) {
#pragma unroll
        for (int q = 0; q < 2; ++q) {
            float s = sacc[nf][q], s2 = s2acc[nf][q];
            s  += __shfl_xor_sync(0xffffffffu, s, 4);
            s  += __shfl_xor_sync(0xffffffffu, s, 8);
            s  += __shfl_xor_sync(0xffffffffu, s, 16);
            s2 += __shfl_xor_sync(0xffffffffu, s2, 4);
            s2 += __shfl_xor_sync(0xffffffffu, s2, 8);
            s2 += __shfl_xor_sync(0xffffffffu, s2, 16);
            if (groupid == 0) {
                int l = n0 + wn * 32 + nf * 8 + tg * 2 + q;
                atomicAdd(&lncur[((size_t)bb * LL + l) * 2 + 0], s);
                atomicAdd(&lncur[((size_t)bb * LL + l) * 2 + 1], s2);
            }
        }
    }
}

// ---------------- kernel 4: lnfix — (sum,sumsq) -> (rs, -mu*rs) ----------------
__global__ void lnfix_kernel(int layer)
{
    int idx = blockIdx.x * blockDim.x + threadIdx.x;
    if (idx >= BB * LL) return;
    float* buf = g_lnst + (layer & 1) * (BB * LL * 2);
    float sum = buf[2 * idx];
    float s2  = buf[2 * idx + 1];
    float mu  = sum * (1.0f / DM);
    float var = s2 * (1.0f / DM) - mu * mu;
    float rs  = rsqrtf(var + 1e-5f);
    buf[2 * idx]     = rs;
    buf[2 * idx + 1] = -mu * rs;
}

// ---------------- kernel 5: mean over L with lazy LN3 --------------------------
__global__ void mean_kernel(const float* __restrict__ ln_g,
                            const float* __restrict__ ln_b)
{
    int ch = blockIdx.x;
    int d = ch & (DM - 1);
    int b = ch >> 9;
    float gd = ln_g[3 * DM + d];
    float bd = ln_b[3 * DM + d];
    const float2* lnp = (const float2*)g_lnst + 1 * (BB * LL) + (size_t)b * LL;
    const float* H = g_h + (size_t)ch * LL;
    float s = 0.f;
    for (int l = threadIdx.x; l < LL; l += 128) {
        float2 lp = lnp[l];
        s += fmaf(fmaf(H[l], lp.x, lp.y), gd, bd);
    }
    __shared__ float sm[128];
    sm[threadIdx.x] = s;
    __syncthreads();
    for (int o = 64; o > 0; o >>= 1) {
        if (threadIdx.x < o) sm[threadIdx.x] += sm[threadIdx.x + o];
        __syncthreads();
    }
    if (threadIdx.x == 0) g_hbar[ch] = sm[0] * (1.0f / LL);
}

// ---------------- kernel 6: stats head + output layout ------------------------
__global__ void stats_kernel(const float* __restrict__ Wstats,
                             const float* __restrict__ bstats,
                             float* __restrict__ out)
{
    int idx = blockIdx.x * blockDim.x + threadIdx.x;
    if (idx >= BB * 2 * LAT) return;
    int b = idx / (2 * LAT);
    int o = idx % (2 * LAT);
    const float* hb = g_hbar + b * DM;
    const float* w  = Wstats + (size_t)o * DM;
    float s = bstats[o];
#pragma unroll 8
    for (int d = 0; d < DM; d++) s = fmaf(hb[d], w[d], s);
    int pos = (o < LAT) ? (b * LAT + o) : (BB * LAT + b * LAT + (o - LAT));
    out[pos] = s;
}

// ---------------- launch ------------------------------------------------------
extern "C" void kernel_launch(void* const* d_in, const int* in_sizes, int n_in,
                              void* d_out, int out_size)
{
    const float* x          = (const float*)d_in[0];
    const float* Wproj      = (const float*)d_in[1];
    const float* bproj      = (const float*)d_in[2];
    const float* pos        = (const float*)d_in[3];
    const float* log_dt     = (const float*)d_in[4];
    const float* log_A_real = (const float*)d_in[5];
    const float* A_imag     = (const float*)d_in[6];
    const float* C_re       = (const float*)d_in[7];
    const float* C_im       = (const float*)d_in[8];
    const float* Dskip      = (const float*)d_in[9];
    const float* Wout       = (const float*)d_in[10];
    const float* bout       = (const float*)d_in[11];
    const float* ln_g       = (const float*)d_in[12];
    const float* ln_b       = (const float*)d_in[13];
    const float* Wstats     = (const float*)d_in[14];
    const float* bstats     = (const float*)d_in[15];
    float* out = (float*)d_out;

    const int gemm_smem = 2 * STAGE;   // 96 KB -> 2 CTAs/SM
    cudaFuncSetAttribute(gemm_mma_kernel,
                         cudaFuncAttributeMaxDynamicSharedMemorySize, gemm_smem);

    precompute_kernel<<<(NLAY * DM * N2C) / 256, 256>>>(log_dt, log_A_real, A_imag, C_re, C_im);
    wsplit_kernel<<<(NLAY * 2 * DM * DM) / 256, 256>>>(Wout);
    proj_kernel<<<(BB * DM * LL) / 256, 256>>>(x, Wproj, bproj, pos);

    for (int layer = 0; layer < NLAY; ++layer) {
        scanA_kernel<<<(BB * DM * (NCH - 1) * 8) / 256, 256>>>(ln_g, ln_b, layer);
        scanC_kernel<<<dim3(NCH, (BB * DM) / 32), 256>>>(Dskip, ln_g, ln_b, layer);
        dim3 ggrid(LL / 128, DM / 64, BB);
        gemm_mma_kernel<<<ggrid, 256, gemm_smem>>>(bout, ln_g, ln_b, layer);
        lnfix_kernel<<<(BB * LL) / 256, 256>>>(layer);
    }

    mean_kernel<<<BB * DM, 128>>>(ln_g, ln_b);
    stats_kernel<<<(BB * 2 * LAT + 255) / 256, 256>>>(Wstats, bstats, out);
}